// round 16
// baseline (speedup 1.0000x reference)
#include <cuda_runtime.h>

#define NN 50000
#define NE 400000
#define ND 128
#define ED 192
#define HD 256

typedef unsigned long long u64;

// Scratch: allocations banned -> device globals.
__device__ __align__(16) float g_agg[(size_t)NN * HD];   // 51.2 MB
__device__ int g_src[NE];
__device__ int g_dst[NE];
__device__ unsigned g_flag;   // 0 => edge_index payload is int64

// ---- packed f32x2 helpers (FFMA2: 2x fp32 throughput) ----------------------
__device__ __forceinline__ u64 ffma2(u64 a, u64 b, u64 c) {
    u64 d; asm("fma.rn.f32x2 %0, %1, %2, %3;" : "=l"(d) : "l"(a), "l"(b), "l"(c)); return d;
}
__device__ __forceinline__ u64 dup2(float x) {
    u64 d; asm("mov.b64 %0, {%1, %1};" : "=l"(d) : "f"(x)); return d;
}
__device__ __forceinline__ void unpack2(u64 v, float& lo, float& hi) {
    asm("mov.b64 {%0, %1}, %2;" : "=f"(lo), "=f"(hi) : "l"(v));
}
__device__ __forceinline__ void cp16(float* s, const float* g) {
    unsigned sa = (unsigned)__cvta_generic_to_shared(s);
    asm volatile("cp.async.cg.shared.global [%0], [%1], 16;" :: "r"(sa), "l"(g));
}
__device__ __forceinline__ void cp_commit() { asm volatile("cp.async.commit_group;"); }
template<int W> __device__ __forceinline__ void cp_wait() {
    asm volatile("cp.async.wait_group %0;" :: "n"(W));
}
// vector reduction to gmem (no return)
__device__ __forceinline__ void red4(float* p, float a, float b, float c, float d) {
    asm volatile("red.global.add.v4.f32 [%0], {%1,%2,%3,%4};"
                 :: "l"(p), "f"(a), "f"(b), "f"(c), "f"(d) : "memory");
}

// mish(x) = x*tanh(softplus(x)) = x*(u^2+2u)/(u^2+2u+2), u = e^x
__device__ __forceinline__ float mish(float v) {
    if (v > 15.f) return v;
    float u = __expf(v);
    float w = u * (u + 2.f);
    return __fdividef(v * w, w + 2.f);
}

// ---------------- prologue kernels ------------------------------------------
__global__ void zero_agg_kernel() {
    size_t i = (size_t)blockIdx.x * blockDim.x + threadIdx.x;   // exact cover
    ((float4*)g_agg)[i] = make_float4(0.f, 0.f, 0.f, 0.f);
    if (i == 0) g_flag = 0u;
}

__global__ void detect_kernel(const unsigned* __restrict__ w) {
    unsigned loc = 0;
    for (int i = blockIdx.x * blockDim.x + threadIdx.x; i < NE;
         i += gridDim.x * blockDim.x)
        loc |= w[2 * i + 1];
    if (__syncthreads_or(loc != 0))
        if (threadIdx.x == 0) atomicOr(&g_flag, 1u);
}

__global__ void convert_kernel(const void* __restrict__ ei) {
    int i = blockIdx.x * blockDim.x + threadIdx.x;
    if (i >= NE) return;
    if (g_flag == 0u) {                              // int64 payload
        const long long* p = (const long long*)ei;
        g_src[i] = (int)p[i];
        g_dst[i] = (int)p[NE + i];
    } else {                                         // int32 payload
        const int* p = (const int*)ei;
        g_src[i] = p[i];
        g_dst[i] = p[NE + i];
    }
}

// ---------------- fused edge-message kernel ---------------------------------
// 64 edges/CTA, 256 threads, thread tile 8x8 (f32x2 accs).
// BOTH GEMMs use the striped warp mapping: cxa = warp*4 + (lane&3) (32-col
// stripe per warp -> B row is a 4-address broadcast, not 32), cya = (lane>>2).
// Hidden tile stored TRANSPOSED Ht[k][row] so the GEMM2 A-read is contiguous
// per thread (same shape as GEMM1's A-read).
// smem (floats): [0,4096)       A dbuf / GEMM2 W2 buf1
//                [4096,20480)   B dbuf / Ht[256][64]
//                [20480,24576)  W2 buf0
// Total 96 KB -> 2 CTAs/SM.
#define EB_OFF 4096
#define EW_OFF 20480
#define EDGE_SMEM (24576 * 4)

__global__ void __launch_bounds__(256, 2)
edge_kernel(const float* __restrict__ x, const float* __restrict__ ea,
            const float* __restrict__ W1, const float* __restrict__ b1,
            const float* __restrict__ W2, const float* __restrict__ b2)
{
    extern __shared__ float sm[];
    __shared__ int sdst[64];

    const int tid = threadIdx.x;
    const int cxa = ((tid >> 5) << 2) | (tid & 3);   // striped col-group
    const int cya = (tid >> 2) & 7;                  // row-group
    const int e = tid & 63;       // gather: edge within CTA
    const int part = tid >> 6;    // gather: 4 threads per edge, 8 k each

    const int eg = blockIdx.x * 64 + e;
    const int sidx = g_src[eg], didx = g_dst[eg];
    if (part == 0) sdst[e] = didx;
    const float* xd  = x + (size_t)didx * ND;
    const float* xs  = x + (size_t)sidx * ND;
    const float* eap = ea + (size_t)eg * ED;

    // prologue: gather chunk 0, prefetch W1 chunk 0
    {
        int kb = part * 8;
        const float* p = xd + kb;   // chunk 0 always in x[dst]
        float4 r0 = *(const float4*)p, r1 = *(const float4*)(p + 4);
        float* a = sm + (part * 8) * 64 + e;
        a[0] = r0.x; a[64] = r0.y; a[128] = r0.z; a[192] = r0.w;
        a[256] = r1.x; a[320] = r1.y; a[384] = r1.z; a[448] = r1.w;
    }
    #pragma unroll
    for (int i = 0; i < 8; ++i) { int j = tid + 256 * i; cp16(sm + EB_OFF + j * 4, W1 + j * 4); }
    cp_commit();

    u64 acc[8][4];
    {
        const u64* bp = (const u64*)b1 + cxa * 4;
        #pragma unroll
        for (int j = 0; j < 4; ++j) {
            u64 bv = bp[j];
            #pragma unroll
            for (int i = 0; i < 8; ++i) acc[i][j] = bv;
        }
    }

    // GEMM1: [64 x 448] @ [448 x 256], 14 k-chunks of 32
    #pragma unroll 1
    for (int s = 0; s < 14; ++s) {
        cp_wait<0>();
        __syncthreads();
        float4 r0, r1;
        const bool more = (s + 1 < 14);
        if (more) {
            const float* g = W1 + (s + 1) * 8192;
            float* buf = sm + EB_OFF + ((s + 1) & 1) * 8192;
            #pragma unroll
            for (int i = 0; i < 8; ++i) { int j = tid + 256 * i; cp16(buf + j * 4, g + j * 4); }
            cp_commit();
            int kb = 32 * (s + 1) + part * 8;
            const float* p = (kb < 128) ? xd + kb
                           : (kb < 256) ? xs + (kb - 128)
                                        : eap + (kb - 256);
            r0 = *(const float4*)p; r1 = *(const float4*)(p + 4);
        } else {
            // prefetch W2 chunk 0 into the idle EW region
            #pragma unroll
            for (int i = 0; i < 4; ++i) { int j = tid + 256 * i; cp16(sm + EW_OFF + j * 4, W2 + j * 4); }
            cp_commit();
        }
        const float* Asb = sm + (s & 1) * 2048;
        const float* Bsb = sm + EB_OFF + (s & 1) * 8192;
        #pragma unroll 4
        for (int kk = 0; kk < 32; ++kk) {
            const float* arow = Asb + kk * 64 + cya * 8;
            float4 aA = *(const float4*)arow;
            float4 aB = *(const float4*)(arow + 4);
            const ulonglong2* brow = (const ulonglong2*)(Bsb + kk * 256 + cxa * 8);
            ulonglong2 B0 = brow[0], B1 = brow[1];
            float av[8] = {aA.x, aA.y, aA.z, aA.w, aB.x, aB.y, aB.z, aB.w};
            #pragma unroll
            for (int i = 0; i < 8; ++i) {
                u64 ad = dup2(av[i]);
                acc[i][0] = ffma2(B0.x, ad, acc[i][0]);
                acc[i][1] = ffma2(B0.y, ad, acc[i][1]);
                acc[i][2] = ffma2(B1.x, ad, acc[i][2]);
                acc[i][3] = ffma2(B1.y, ad, acc[i][3]);
            }
        }
        if (more) {
            float* a = sm + ((s + 1) & 1) * 2048 + (part * 8) * 64 + e;
            a[0] = r0.x; a[64] = r0.y; a[128] = r0.z; a[192] = r0.w;
            a[256] = r1.x; a[320] = r1.y; a[384] = r1.z; a[448] = r1.w;
        }
    }

    __syncthreads();   // all GEMM1 smem reads done before Ht overwrites B region

    // mish -> Ht[256][64] (transposed) in the B region
    float* Hs = sm + EB_OFF;
    {
        float hv[8][8];
        #pragma unroll
        for (int i = 0; i < 8; ++i) {
            float v[8];
            #pragma unroll
            for (int j = 0; j < 4; ++j) unpack2(acc[i][j], v[2 * j], v[2 * j + 1]);
            #pragma unroll
            for (int j = 0; j < 8; ++j) hv[i][j] = mish(v[j]);
        }
        #pragma unroll
        for (int j = 0; j < 8; ++j) {
            float* hp = Hs + (cxa * 8 + j) * 64 + cya * 8;
            *(float4*)hp       = make_float4(hv[0][j], hv[1][j], hv[2][j], hv[3][j]);
            *(float4*)(hp + 4) = make_float4(hv[4][j], hv[5][j], hv[6][j], hv[7][j]);
        }
    }

    {
        const u64* bp = (const u64*)b2 + cxa * 4;
        #pragma unroll
        for (int j = 0; j < 4; ++j) {
            u64 bv = bp[j];
            #pragma unroll
            for (int i = 0; i < 8; ++i) acc[i][j] = bv;
        }
    }

    // GEMM2: [64 x 256] @ [256 x 256], 16 k-chunks of 16, striped mapping.
    // A-read from Ht is contiguous per thread, identical shape to GEMM1.
    #pragma unroll 1
    for (int s = 0; s < 16; ++s) {
        cp_wait<0>();
        __syncthreads();
        if (s + 1 < 16) {
            const float* g = W2 + (s + 1) * 4096;
            float* buf = ((s + 1) & 1) ? sm : sm + EW_OFF;
            #pragma unroll
            for (int i = 0; i < 4; ++i) { int j = tid + 256 * i; cp16(buf + j * 4, g + j * 4); }
            cp_commit();
        }
        const float* Bsb = (s & 1) ? sm : sm + EW_OFF;
        const float* Hk = Hs + (s * 16) * 64 + cya * 8;
        #pragma unroll 4
        for (int kk = 0; kk < 16; ++kk) {
            const float* arow = Hk + kk * 64;
            float4 aA = *(const float4*)arow;
            float4 aB = *(const float4*)(arow + 4);
            const ulonglong2* brow = (const ulonglong2*)(Bsb + kk * 256 + cxa * 8);
            ulonglong2 B0 = brow[0], B1 = brow[1];
            float av[8] = {aA.x, aA.y, aA.z, aA.w, aB.x, aB.y, aB.z, aB.w};
            #pragma unroll
            for (int i = 0; i < 8; ++i) {
                u64 ad = dup2(av[i]);
                acc[i][0] = ffma2(B0.x, ad, acc[i][0]);
                acc[i][1] = ffma2(B0.y, ad, acc[i][1]);
                acc[i][2] = ffma2(B1.x, ad, acc[i][2]);
                acc[i][3] = ffma2(B1.y, ad, acc[i][3]);
            }
        }
    }

    // scatter-add msg into g_agg[dst] via vector REDG (striped layout)
    #pragma unroll
    for (int i = 0; i < 8; ++i) {
        float v[8];
        #pragma unroll
        for (int j = 0; j < 4; ++j) unpack2(acc[i][j], v[2 * j], v[2 * j + 1]);
        float* p = g_agg + (size_t)sdst[cya * 8 + i] * HD + cxa * 8;
        red4(p,     v[0], v[1], v[2], v[3]);
        red4(p + 4, v[4], v[5], v[6], v[7]);
    }
}

// ---------------- fused node-update kernel ----------------------------------
// 64 nodes/CTA, 256 threads. GEMM1 tile 8x8 striped mapping (like edge);
// GEMM2 tile 4x8 + LN keep the old mapping (shfl groups need it).
#define NODE_SMEM (24576 * 4)

__global__ void __launch_bounds__(256, 2)
node_kernel(const float* __restrict__ x,
            const float* __restrict__ U1, const float* __restrict__ c1,
            const float* __restrict__ U2, const float* __restrict__ c2,
            const float* __restrict__ gamma, const float* __restrict__ beta,
            float* __restrict__ out)
{
    extern __shared__ float sm[];
    const int tid = threadIdx.x;
    const int cxa = ((tid >> 5) << 2) | (tid & 3);
    const int cya = (tid >> 2) & 7;
    const int e = tid & 63, part = tid >> 6;
    const int nbase = blockIdx.x * 64;

    int gnode = nbase + e;
    if (gnode >= NN) gnode = 0;
    const float* xp = x + (size_t)gnode * ND;
    const float* ap = g_agg + (size_t)gnode * HD;

    // prologue: gather chunk 0, prefetch U1 chunk 0
    {
        int kb = part * 8;
        const float* p = xp + kb;
        float4 r0 = *(const float4*)p, r1 = *(const float4*)(p + 4);
        float* a = sm + (part * 8) * 64 + e;
        a[0] = r0.x; a[64] = r0.y; a[128] = r0.z; a[192] = r0.w;
        a[256] = r1.x; a[320] = r1.y; a[384] = r1.z; a[448] = r1.w;
    }
    #pragma unroll
    for (int i = 0; i < 8; ++i) { int j = tid + 256 * i; cp16(sm + EB_OFF + j * 4, U1 + j * 4); }
    cp_commit();

    u64 acc[8][4];
    {
        const u64* bp = (const u64*)c1 + cxa * 4;
        #pragma unroll
        for (int j = 0; j < 4; ++j) {
            u64 bv = bp[j];
            #pragma unroll
            for (int i = 0; i < 8; ++i) acc[i][j] = bv;
        }
    }

    // GEMM1: [64 x 384] @ [384 x 256], 12 k-chunks of 32
    #pragma unroll 1
    for (int s = 0; s < 12; ++s) {
        cp_wait<0>();
        __syncthreads();
        float4 r0, r1;
        const bool more = (s + 1 < 12);
        if (more) {
            const float* g = U1 + (s + 1) * 8192;
            float* buf = sm + EB_OFF + ((s + 1) & 1) * 8192;
            #pragma unroll
            for (int i = 0; i < 8; ++i) { int j = tid + 256 * i; cp16(buf + j * 4, g + j * 4); }
            cp_commit();
            int kb = 32 * (s + 1) + part * 8;
            const float* p = (kb < 128) ? xp + kb : ap + (kb - 128);
            r0 = *(const float4*)p; r1 = *(const float4*)(p + 4);
        } else {
            #pragma unroll
            for (int i = 0; i < 4; ++i) { int j = tid + 256 * i; cp16(sm + EW_OFF + j * 4, U2 + j * 4); }
            cp_commit();
        }
        const float* Asb = sm + (s & 1) * 2048;
        const float* Bsb = sm + EB_OFF + (s & 1) * 8192;
        #pragma unroll 4
        for (int kk = 0; kk < 32; ++kk) {
            const float* arow = Asb + kk * 64 + cya * 8;
            float4 aA = *(const float4*)arow;
            float4 aB = *(const float4*)(arow + 4);
            const ulonglong2* brow = (const ulonglong2*)(Bsb + kk * 256 + cxa * 8);
            ulonglong2 B0 = brow[0], B1 = brow[1];
            float av[8] = {aA.x, aA.y, aA.z, aA.w, aB.x, aB.y, aB.z, aB.w};
            #pragma unroll
            for (int i = 0; i < 8; ++i) {
                u64 ad = dup2(av[i]);
                acc[i][0] = ffma2(B0.x, ad, acc[i][0]);
                acc[i][1] = ffma2(B0.y, ad, acc[i][1]);
                acc[i][2] = ffma2(B1.x, ad, acc[i][2]);
                acc[i][3] = ffma2(B1.y, ad, acc[i][3]);
            }
        }
        if (more) {
            float* a = sm + ((s + 1) & 1) * 2048 + (part * 8) * 64 + e;
            a[0] = r0.x; a[64] = r0.y; a[128] = r0.z; a[192] = r0.w;
            a[256] = r1.x; a[320] = r1.y; a[384] = r1.z; a[448] = r1.w;
        }
    }
    __syncthreads();

    // mish -> H[64][256] (row-major, GEMM1 striped mapping)
    float* Hs = sm + EB_OFF;
    #pragma unroll
    for (int i = 0; i < 8; ++i) {
        float v[8];
        #pragma unroll
        for (int j = 0; j < 4; ++j) unpack2(acc[i][j], v[2 * j], v[2 * j + 1]);
        #pragma unroll
        for (int j = 0; j < 8; ++j) v[j] = mish(v[j]);
        float* hp = Hs + (cya * 8 + i) * 256 + cxa * 8;
        *(float4*)hp       = make_float4(v[0], v[1], v[2], v[3]);
        *(float4*)(hp + 4) = make_float4(v[4], v[5], v[6], v[7]);
    }

    // GEMM2: [64 x 256] @ [256 x 128], 8 k-chunks of 32, tile 4x8 (old map)
    const int cx2 = tid & 15, cy2 = tid >> 4;
    u64 acc2[4][4];
    {
        const u64* bp = (const u64*)c2 + cx2 * 4;
        #pragma unroll
        for (int j = 0; j < 4; ++j) {
            u64 bv = bp[j];
            #pragma unroll
            for (int i = 0; i < 4; ++i) acc2[i][j] = bv;
        }
    }

    #pragma unroll 1
    for (int s = 0; s < 8; ++s) {
        cp_wait<0>();
        __syncthreads();
        if (s + 1 < 8) {
            const float* g = U2 + (s + 1) * 4096;
            float* buf = ((s + 1) & 1) ? sm : sm + EW_OFF;
            #pragma unroll
            for (int i = 0; i < 4; ++i) { int j = tid + 256 * i; cp16(buf + j * 4, g + j * 4); }
            cp_commit();
        }
        const float* Bsb = (s & 1) ? sm : sm + EW_OFF;
        const float* hbase = Hs + (cy2 * 4) * 256;
        #pragma unroll 4
        for (int kk = 0; kk < 32; ++kk) {
            int k = s * 32 + kk;
            const ulonglong2* brow = (const ulonglong2*)(Bsb + kk * 128 + cx2 * 8);
            ulonglong2 B0 = brow[0], B1 = brow[1];
            #pragma unroll
            for (int i = 0; i < 4; ++i) {
                u64 ad = dup2(hbase[i * 256 + k]);
                acc2[i][0] = ffma2(B0.x, ad, acc2[i][0]);
                acc2[i][1] = ffma2(B0.y, ad, acc2[i][1]);
                acc2[i][2] = ffma2(B1.x, ad, acc2[i][2]);
                acc2[i][3] = ffma2(B1.y, ad, acc2[i][3]);
            }
        }
    }

    // residual + LayerNorm in registers (16-lane shfl groups per row)
    float g8[8], be8[8];
    {
        float4 t0 = *(const float4*)(gamma + cx2 * 8);
        float4 t1 = *(const float4*)(gamma + cx2 * 8 + 4);
        g8[0]=t0.x; g8[1]=t0.y; g8[2]=t0.z; g8[3]=t0.w;
        g8[4]=t1.x; g8[5]=t1.y; g8[6]=t1.z; g8[7]=t1.w;
        float4 u0 = *(const float4*)(beta + cx2 * 8);
        float4 u1 = *(const float4*)(beta + cx2 * 8 + 4);
        be8[0]=u0.x; be8[1]=u0.y; be8[2]=u0.z; be8[3]=u0.w;
        be8[4]=u1.x; be8[5]=u1.y; be8[6]=u1.z; be8[7]=u1.w;
    }
    #pragma unroll
    for (int i = 0; i < 4; ++i) {
        const int row = cy2 * 4 + i;
        const int node = nbase + row;
        float v[8];
        #pragma unroll
        for (int j = 0; j < 4; ++j) unpack2(acc2[i][j], v[2 * j], v[2 * j + 1]);
        if (node < NN) {
            const float* xr = x + (size_t)node * ND + cx2 * 8;
            float4 r0 = *(const float4*)xr, r1 = *(const float4*)(xr + 4);
            v[0]+=r0.x; v[1]+=r0.y; v[2]+=r0.z; v[3]+=r0.w;
            v[4]+=r1.x; v[5]+=r1.y; v[6]+=r1.z; v[7]+=r1.w;
        }
        float s1 = 0.f, s2 = 0.f;
        #pragma unroll
        for (int j = 0; j < 8; ++j) { s1 += v[j]; s2 += v[j] * v[j]; }
        #pragma unroll
        for (int off = 1; off < 16; off <<= 1) {
            s1 += __shfl_xor_sync(0xFFFFFFFFu, s1, off);
            s2 += __shfl_xor_sync(0xFFFFFFFFu, s2, off);
        }
        float mu = s1 * (1.f / 128.f);
        float var = s2 * (1.f / 128.f) - mu * mu;
        float r = rsqrtf(var + 1e-5f);
        if (node < NN) {
            float* op = out + (size_t)node * ND + cx2 * 8;
            float4 o0, o1;
            o0.x = (v[0]-mu)*r*g8[0]+be8[0]; o0.y = (v[1]-mu)*r*g8[1]+be8[1];
            o0.z = (v[2]-mu)*r*g8[2]+be8[2]; o0.w = (v[3]-mu)*r*g8[3]+be8[3];
            o1.x = (v[4]-mu)*r*g8[4]+be8[4]; o1.y = (v[5]-mu)*r*g8[5]+be8[5];
            o1.z = (v[6]-mu)*r*g8[6]+be8[6]; o1.w = (v[7]-mu)*r*g8[7]+be8[7];
            *(float4*)op       = o0;
            *(float4*)(op + 4) = o1;
        }
    }
}

// ---------------- launch ------------------------------------------------
extern "C" void kernel_launch(void* const* d_in, const int* in_sizes, int n_in,
                              void* d_out, int out_size) {
    (void)in_sizes; (void)n_in; (void)out_size;
    const float* x     = (const float*)d_in[0];
    const void*  ei    = d_in[1];
    const float* ea    = (const float*)d_in[2];
    const float* W1    = (const float*)d_in[3];
    const float* b1    = (const float*)d_in[4];
    const float* W2    = (const float*)d_in[5];
    const float* b2    = (const float*)d_in[6];
    const float* U1    = (const float*)d_in[7];
    const float* c1    = (const float*)d_in[8];
    const float* U2    = (const float*)d_in[9];
    const float* c2    = (const float*)d_in[10];
    const float* gamma = (const float*)d_in[11];
    const float* beta  = (const float*)d_in[12];
    float* out = (float*)d_out;

    static bool attr_set = false;
    if (!attr_set) {
        cudaFuncSetAttribute(edge_kernel, cudaFuncAttributeMaxDynamicSharedMemorySize, EDGE_SMEM);
        cudaFuncSetAttribute(node_kernel, cudaFuncAttributeMaxDynamicSharedMemorySize, NODE_SMEM);
        attr_set = true;
    }

    zero_agg_kernel<<<12500, 256>>>();
    detect_kernel<<<128, 256>>>((const unsigned*)ei);
    convert_kernel<<<(NE + 255) / 256, 256>>>(ei);
    edge_kernel<<<NE / 64, 256, EDGE_SMEM>>>(x, ea, W1, b1, W2, b2);
    node_kernel<<<(NN + 63) / 64, 256, NODE_SMEM>>>(x, U1, c1, U2, c2, gamma, beta, out);
}

// round 17
// speedup vs baseline: 1.4703x; 1.4703x over previous
#include <cuda_runtime.h>
#include <cuda_bf16.h>

#define NN 50000
#define NE 400000
#define ND 128
#define ED 192
#define HD 256

typedef unsigned long long u64;
typedef unsigned int u32;

// Scratch: allocations banned -> device globals.
__device__ __align__(16) float g_agg[(size_t)NN * HD];
__device__ int g_src[NE];
__device__ int g_dst[NE];
__device__ unsigned g_flag;
// packed bf16 hi/lo weight images: k32 chunks, each {hi 16KB, lo 16KB}, XOR-swizzled
__device__ __align__(16) unsigned char g_w1p[14 * 32768];
__device__ __align__(16) unsigned char g_w2p[8 * 32768];

// ---- helpers ----------------------------------------------------------------
__device__ __forceinline__ u64 ffma2(u64 a, u64 b, u64 c) {
    u64 d; asm("fma.rn.f32x2 %0, %1, %2, %3;" : "=l"(d) : "l"(a), "l"(b), "l"(c)); return d;
}
__device__ __forceinline__ u64 dup2(float x) {
    u64 d; asm("mov.b64 %0, {%1, %1};" : "=l"(d) : "f"(x)); return d;
}
__device__ __forceinline__ void unpack2(u64 v, float& lo, float& hi) {
    asm("mov.b64 {%0, %1}, %2;" : "=f"(lo), "=f"(hi) : "l"(v));
}
__device__ __forceinline__ void cp16(float* s, const float* g) {
    unsigned sa = (unsigned)__cvta_generic_to_shared(s);
    asm volatile("cp.async.cg.shared.global [%0], [%1], 16;" :: "r"(sa), "l"(g));
}
__device__ __forceinline__ void cp16s(u32 s, const void* g) {
    asm volatile("cp.async.cg.shared.global [%0], [%1], 16;" :: "r"(s), "l"(g));
}
__device__ __forceinline__ void cp_commit() { asm volatile("cp.async.commit_group;"); }
template<int W> __device__ __forceinline__ void cp_wait() {
    asm volatile("cp.async.wait_group %0;" :: "n"(W));
}
__device__ __forceinline__ void red4(float* p, float a, float b, float c, float d) {
    asm volatile("red.global.add.v4.f32 [%0], {%1,%2,%3,%4};"
                 :: "l"(p), "f"(a), "f"(b), "f"(c), "f"(d) : "memory");
}
__device__ __forceinline__ void red2(float* p, float a, float b) {
    asm volatile("red.global.add.v2.f32 [%0], {%1,%2};"
                 :: "l"(p), "f"(a), "f"(b) : "memory");
}
__device__ __forceinline__ float mish(float v) {
    if (v > 15.f) return v;
    float u = __expf(v);
    float w = u * (u + 2.f);
    return __fdividef(v * w, w + 2.f);
}
__device__ __forceinline__ u32 smem_u32(const void* p) { return (u32)__cvta_generic_to_shared(p); }
__device__ __forceinline__ void sts128(u32 a, u32 x, u32 y, u32 z, u32 w) {
    asm volatile("st.shared.v4.b32 [%0], {%1,%2,%3,%4};" :: "r"(a), "r"(x), "r"(y), "r"(z), "r"(w) : "memory");
}
__device__ __forceinline__ void sts32(u32 a, u32 v) {
    asm volatile("st.shared.b32 [%0], %1;" :: "r"(a), "r"(v) : "memory");
}
__device__ __forceinline__ u32 cvt2(float a, float b, float& ra, float& rb) {
    __nv_bfloat162 t = __float22bfloat162_rn(make_float2(a, b));
    float2 f = __bfloat1622float2(t);
    ra = a - f.x; rb = b - f.y;
    return *reinterpret_cast<u32*>(&t);
}
__device__ __forceinline__ u32 cvt2o(float a, float b) {
    __nv_bfloat162 t = __float22bfloat162_rn(make_float2(a, b));
    return *reinterpret_cast<u32*>(&t);
}
__device__ __forceinline__ void ldsm4(u32 a, u32& r0, u32& r1, u32& r2, u32& r3) {
    asm volatile("ldmatrix.sync.aligned.m8n8.x4.shared.b16 {%0,%1,%2,%3}, [%4];"
                 : "=r"(r0), "=r"(r1), "=r"(r2), "=r"(r3) : "r"(a));
}
__device__ __forceinline__ void ldsm4t(u32 a, u32& r0, u32& r1, u32& r2, u32& r3) {
    asm volatile("ldmatrix.sync.aligned.m8n8.x4.trans.shared.b16 {%0,%1,%2,%3}, [%4];"
                 : "=r"(r0), "=r"(r1), "=r"(r2), "=r"(r3) : "r"(a));
}
__device__ __forceinline__ void mma16816(float* d, const u32* a, u32 b0, u32 b1) {
    asm volatile("mma.sync.aligned.m16n8k16.row.col.f32.bf16.bf16.f32 "
                 "{%0,%1,%2,%3}, {%4,%5,%6,%7}, {%8,%9}, {%0,%1,%2,%3};"
                 : "+f"(d[0]), "+f"(d[1]), "+f"(d[2]), "+f"(d[3])
                 : "r"(a[0]), "r"(a[1]), "r"(a[2]), "r"(a[3]), "r"(b0), "r"(b1));
}

// ---- prologue kernels ---------------------------------------------------------
__global__ void zero_agg_kernel() {
    size_t i = (size_t)blockIdx.x * blockDim.x + threadIdx.x;
    ((float4*)g_agg)[i] = make_float4(0.f, 0.f, 0.f, 0.f);
    if (i == 0) g_flag = 0u;
}
__global__ void detect_kernel(const unsigned* __restrict__ w) {
    unsigned loc = 0;
    for (int i = blockIdx.x * blockDim.x + threadIdx.x; i < NE; i += gridDim.x * blockDim.x)
        loc |= w[2 * i + 1];
    if (__syncthreads_or(loc != 0))
        if (threadIdx.x == 0) atomicOr(&g_flag, 1u);
}
__global__ void convert_kernel(const void* __restrict__ ei) {
    int i = blockIdx.x * blockDim.x + threadIdx.x;
    if (i >= NE) return;
    if (g_flag == 0u) {
        const long long* p = (const long long*)ei;
        g_src[i] = (int)p[i]; g_dst[i] = (int)p[NE + i];
    } else {
        const int* p = (const int*)ei;
        g_src[i] = p[i]; g_dst[i] = p[NE + i];
    }
}
// pack W[k][256] fp32 -> k32 chunks: hi/lo bf16 planes, rows 512B, block XOR swizzle
__device__ __forceinline__ void pack_one(const float* W, unsigned char* dst, int idx) {
    int k = idx >> 8, n = idx & 255;
    float v = W[idx];
    __nv_bfloat16 h = __float2bfloat16(v);
    __nv_bfloat16 l = __float2bfloat16(v - __bfloat162float(h));
    int s = k >> 5, kk = k & 31;
    u32 off = (u32)(s * 32768 + kk * 512 + (((n >> 3) ^ (kk & 7)) << 4) + (n & 7) * 2);
    *(unsigned short*)(dst + off)         = *(unsigned short*)&h;
    *(unsigned short*)(dst + off + 16384) = *(unsigned short*)&l;
}
__global__ void pack_w1_kernel(const float* __restrict__ W) {
    pack_one(W, g_w1p, blockIdx.x * 256 + threadIdx.x);
}
__global__ void pack_w2_kernel(const float* __restrict__ W) {
    pack_one(W, g_w2p, blockIdx.x * 256 + threadIdx.x);
}

// ---- edge kernel: mma.sync bf16x3 ----------------------------------------------
// 64 edges/CTA, 256 thr (8 warps, warp tile 32m x 64n). dyn smem:
//   [0,65536)       W dbuf: buf b at b*32768, {hi 16K, lo 16K}
//   [65536,86016)   A dbuf: buf b at +b*10240, {hi 5120 (64 rows x 80B), lo 5120}
//   [65536,133120)  Ht (GEMM2 A): hi 64x528B = 33792, lo +33792  (overlays A dbuf)
#define AOFF 65536
#define HOFF 65536
#define HLO 33792
#define EDYN 133120

__global__ void __launch_bounds__(256, 1)
edge_kernel(const float* __restrict__ x, const float* __restrict__ ea,
            const float* __restrict__ b1v, const float* __restrict__ b2v)
{
    extern __shared__ char sm8[];
    __shared__ int sdst[64];
    __shared__ float sb1[256], sb2[256];
    const u32 SB = smem_u32(sm8);
    const int tid = threadIdx.x, warp = tid >> 5, lane = tid & 31;
    const int mg = (warp & 1) << 5, cg = (warp >> 1) << 6;
    const int e = tid & 63, part = tid >> 6;
    const int eg = blockIdx.x * 64 + e;
    const int sidx = g_src[eg], didx = g_dst[eg];
    if (part == 0) sdst[e] = didx;
    sb1[tid] = b1v[tid]; sb2[tid] = b2v[tid];
    const float* xd  = x + (size_t)didx * ND;
    const float* xs  = x + (size_t)sidx * ND;
    const float* eap = ea + (size_t)eg * ED;

    const int lr = lane & 7, ls8 = (lane >> 3) & 1, ls16 = lane >> 4;
    const int arow = lr + ls8 * 8;          // A ldmatrix row within m16 tile
    const int bkr0 = lr + ls8 * 8;          // B ldmatrix k-row within k16
    const int jbb  = (cg >> 3) + ls16;      // B n-block base (+ng*2)

    float acc[16][4];
    #pragma unroll
    for (int t = 0; t < 16; ++t) { acc[t][0] = acc[t][1] = acc[t][2] = acc[t][3] = 0.f; }

    auto gatherA = [&](int s, int buf) {
        int kb = s * 32 + part * 8;
        const float* p = (kb < 128) ? xd + kb : (kb < 256) ? xs + (kb - 128) : eap + (kb - 256);
        float4 va = *(const float4*)p, vb = *(const float4*)(p + 4);
        float r0, r1, r2, r3, r4, r5, r6, r7;
        u32 h0 = cvt2(va.x, va.y, r0, r1), h1 = cvt2(va.z, va.w, r2, r3);
        u32 h2 = cvt2(vb.x, vb.y, r4, r5), h3 = cvt2(vb.z, vb.w, r6, r7);
        u32 l0 = cvt2o(r0, r1), l1 = cvt2o(r2, r3), l2 = cvt2o(r4, r5), l3 = cvt2o(r6, r7);
        u32 a = SB + AOFF + (u32)(buf * 10240 + e * 80 + part * 16);
        sts128(a, h0, h1, h2, h3);
        sts128(a + 5120, l0, l1, l2, l3);
    };
    auto cpW = [&](const unsigned char* g, int chunk, int buf) {
        const unsigned char* src = g + chunk * 32768;
        u32 dst = SB + (u32)(buf * 32768);
        #pragma unroll
        for (int i = 0; i < 8; ++i) { u32 o = (u32)(tid + 256 * i) * 16; cp16s(dst + o, src + o); }
        cp_commit();
    };
    // one k16 step: A from (ahp/alp, stride astr, byte offset ko2), B from W buf (whp/wlp, k-row ko)
    auto k16 = [&](u32 ahp, u32 alp, int astr, int ko2, u32 whp, u32 wlp, int ko) {
        u32 ah[2][4], al[2][4];
        #pragma unroll
        for (int mt = 0; mt < 2; ++mt) {
            u32 ro = (u32)((mg + mt * 16 + arow) * astr) + (u32)ko2 + (u32)(ls16 * 16);
            ldsm4(ahp + ro, ah[mt][0], ah[mt][1], ah[mt][2], ah[mt][3]);
            ldsm4(alp + ro, al[mt][0], al[mt][1], al[mt][2], al[mt][3]);
        }
        const int kr = ko + bkr0;
        const u32 krow = (u32)(kr * 512);
        #pragma unroll
        for (int ng = 0; ng < 4; ++ng) {
            u32 bo = krow + ((u32)((jbb + ng * 2) ^ (kr & 7)) << 4);
            u32 bh0, bh1, bh2, bh3, bl0, bl1, bl2, bl3;
            ldsm4t(whp + bo, bh0, bh1, bh2, bh3);
            ldsm4t(wlp + bo, bl0, bl1, bl2, bl3);
            #pragma unroll
            for (int mt = 0; mt < 2; ++mt) {
                int t = mt * 8 + ng * 2;
                mma16816(acc[t],     ah[mt], bh0, bh1);
                mma16816(acc[t],     al[mt], bh0, bh1);
                mma16816(acc[t],     ah[mt], bl0, bl1);
                mma16816(acc[t + 1], ah[mt], bh2, bh3);
                mma16816(acc[t + 1], al[mt], bh2, bh3);
                mma16816(acc[t + 1], ah[mt], bl2, bl3);
            }
        }
    };

    // ---- GEMM1: K=448, 14 k32 stages ----
    gatherA(0, 0);
    cpW(g_w1p, 0, 0);
    #pragma unroll 1
    for (int s = 0; s < 14; ++s) {
        cp_wait<0>();
        __syncthreads();
        if (s + 1 < 14) { gatherA(s + 1, (s + 1) & 1); cpW(g_w1p, s + 1, (s + 1) & 1); }
        u32 ab = SB + AOFF + (u32)((s & 1) * 10240);
        u32 wb = SB + (u32)((s & 1) * 32768);
        k16(ab, ab + 5120, 80, 0,  wb, wb + 16384, 0);
        k16(ab, ab + 5120, 80, 32, wb, wb + 16384, 16);
    }

    // W2 chunk 0 -> buf0 (safe: stage 13 read buf1 only)
    cpW(g_w2p, 0, 0);
    __syncthreads();   // all GEMM1 smem reads done before Ht overwrites A region

    // mid-epilogue: +b1, mish, bf16 split -> Ht
    #pragma unroll
    for (int t = 0; t < 16; ++t) {
        int mt = t >> 3, nt = t & 7;
        int r0 = mg + mt * 16 + (lane >> 2);
        int c  = cg + nt * 8 + ((lane & 3) << 1);
        float2 bb = *(const float2*)(sb1 + c);
        float v00 = mish(acc[t][0] + bb.x), v01 = mish(acc[t][1] + bb.y);
        float v10 = mish(acc[t][2] + bb.x), v11 = mish(acc[t][3] + bb.y);
        float q0, q1, q2, q3;
        u32 h0 = cvt2(v00, v01, q0, q1), h1 = cvt2(v10, v11, q2, q3);
        u32 l0 = cvt2o(q0, q1), l1 = cvt2o(q2, q3);
        u32 ha = SB + HOFF + (u32)(r0 * 528 + c * 2);
        sts32(ha, h0);             sts32(ha + HLO, l0);
        sts32(ha + 8 * 528, h1);   sts32(ha + 8 * 528 + HLO, l1);
        acc[t][0] = acc[t][1] = acc[t][2] = acc[t][3] = 0.f;
    }

    // ---- GEMM2: K=256, 8 k32 stages (A = Ht static) ----
    #pragma unroll 1
    for (int s = 0; s < 8; ++s) {
        cp_wait<0>();
        __syncthreads();
        if (s + 1 < 8) cpW(g_w2p, s + 1, (s + 1) & 1);
        u32 wb = SB + (u32)((s & 1) * 32768);
        u32 hb = SB + HOFF;
        k16(hb, hb + HLO, 528, s * 64,      wb, wb + 16384, 0);
        k16(hb, hb + HLO, 528, s * 64 + 32, wb, wb + 16384, 16);
    }

    // scatter epilogue: +b2 -> red.v2 into g_agg[dst]
    int dsts[2][2];
    #pragma unroll
    for (int mt = 0; mt < 2; ++mt) {
        int r = mg + mt * 16 + (lane >> 2);
        dsts[mt][0] = sdst[r]; dsts[mt][1] = sdst[r + 8];
    }
    #pragma unroll
    for (int t = 0; t < 16; ++t) {
        int mt = t >> 3, nt = t & 7;
        int c = cg + nt * 8 + ((lane & 3) << 1);
        float2 bb = *(const float2*)(sb2 + c);
        float* p0 = g_agg + (size_t)dsts[mt][0] * HD + c;
        float* p1 = g_agg + (size_t)dsts[mt][1] * HD + c;
        red2(p0, acc[t][0] + bb.x, acc[t][1] + bb.y);
        red2(p1, acc[t][2] + bb.x, acc[t][3] + bb.y);
    }
}

// ---- node kernel (SIMT f32x2, unchanged from R15) --------------------------------
#define EB_OFF 4096
#define EW_OFF 20480
#define NODE_SMEM (24576 * 4)

__global__ void __launch_bounds__(256, 2)
node_kernel(const float* __restrict__ x,
            const float* __restrict__ U1, const float* __restrict__ c1,
            const float* __restrict__ U2, const float* __restrict__ c2,
            const float* __restrict__ gamma, const float* __restrict__ beta,
            float* __restrict__ out)
{
    extern __shared__ float sm[];
    const int tid = threadIdx.x;
    const int cxa = ((tid >> 5) << 2) | (tid & 3);
    const int cya = (tid >> 2) & 7;
    const int e = tid & 63, part = tid >> 6;
    const int nbase = blockIdx.x * 64;

    int gnode = nbase + e;
    if (gnode >= NN) gnode = 0;
    const float* xp = x + (size_t)gnode * ND;
    const float* ap = g_agg + (size_t)gnode * HD;

    {
        int kb = part * 8;
        const float* p = xp + kb;
        float4 r0 = *(const float4*)p, r1 = *(const float4*)(p + 4);
        float* a = sm + (part * 8) * 64 + e;
        a[0] = r0.x; a[64] = r0.y; a[128] = r0.z; a[192] = r0.w;
        a[256] = r1.x; a[320] = r1.y; a[384] = r1.z; a[448] = r1.w;
    }
    #pragma unroll
    for (int i = 0; i < 8; ++i) { int j = tid + 256 * i; cp16(sm + EB_OFF + j * 4, U1 + j * 4); }
    cp_commit();

    u64 acc[8][4];
    {
        const u64* bp = (const u64*)c1 + cxa * 4;
        #pragma unroll
        for (int j = 0; j < 4; ++j) {
            u64 bv = bp[j];
            #pragma unroll
            for (int i = 0; i < 8; ++i) acc[i][j] = bv;
        }
    }

    #pragma unroll 1
    for (int s = 0; s < 12; ++s) {
        cp_wait<0>();
        __syncthreads();
        float4 r0, r1;
        const bool more = (s + 1 < 12);
        if (more) {
            const float* g = U1 + (s + 1) * 8192;
            float* buf = sm + EB_OFF + ((s + 1) & 1) * 8192;
            #pragma unroll
            for (int i = 0; i < 8; ++i) { int j = tid + 256 * i; cp16(buf + j * 4, g + j * 4); }
            cp_commit();
            int kb = 32 * (s + 1) + part * 8;
            const float* p = (kb < 128) ? xp + kb : ap + (kb - 128);
            r0 = *(const float4*)p; r1 = *(const float4*)(p + 4);
        } else {
            #pragma unroll
            for (int i = 0; i < 4; ++i) { int j = tid + 256 * i; cp16(sm + EW_OFF + j * 4, U2 + j * 4); }
            cp_commit();
        }
        const float* Asb = sm + (s & 1) * 2048;
        const float* Bsb = sm + EB_OFF + (s & 1) * 8192;
        #pragma unroll 4
        for (int kk = 0; kk < 32; ++kk) {
            const float* arow = Asb + kk * 64 + cya * 8;
            float4 aA = *(const float4*)arow;
            float4 aB = *(const float4*)(arow + 4);
            const ulonglong2* brow = (const ulonglong2*)(Bsb + kk * 256 + cxa * 8);
            ulonglong2 B0 = brow[0], B1 = brow[1];
            float av[8] = {aA.x, aA.y, aA.z, aA.w, aB.x, aB.y, aB.z, aB.w};
            #pragma unroll
            for (int i = 0; i < 8; ++i) {
                u64 ad = dup2(av[i]);
                acc[i][0] = ffma2(B0.x, ad, acc[i][0]);
                acc[i][1] = ffma2(B0.y, ad, acc[i][1]);
                acc[i][2] = ffma2(B1.x, ad, acc[i][2]);
                acc[i][3] = ffma2(B1.y, ad, acc[i][3]);
            }
        }
        if (more) {
            float* a = sm + ((s + 1) & 1) * 2048 + (part * 8) * 64 + e;
            a[0] = r0.x; a[64] = r0.y; a[128] = r0.z; a[192] = r0.w;
            a[256] = r1.x; a[320] = r1.y; a[384] = r1.z; a[448] = r1.w;
        }
    }
    __syncthreads();

    float* Hs = sm + EB_OFF;
    #pragma unroll
    for (int i = 0; i < 8; ++i) {
        float v[8];
        #pragma unroll
        for (int j = 0; j < 4; ++j) unpack2(acc[i][j], v[2 * j], v[2 * j + 1]);
        #pragma unroll
        for (int j = 0; j < 8; ++j) v[j] = mish(v[j]);
        float* hp = Hs + (cya * 8 + i) * 256 + cxa * 8;
        *(float4*)hp       = make_float4(v[0], v[1], v[2], v[3]);
        *(float4*)(hp + 4) = make_float4(v[4], v[5], v[6], v[7]);
    }

    const int cx2 = tid & 15, cy2 = tid >> 4;
    u64 acc2[4][4];
    {
        const u64* bp = (const u64*)c2 + cx2 * 4;
        #pragma unroll
        for (int j = 0; j < 4; ++j) {
            u64 bv = bp[j];
            #pragma unroll
            for (int i = 0; i < 4; ++i) acc2[i][j] = bv;
        }
    }

    #pragma unroll 1
    for (int s = 0; s < 8; ++s) {
        cp_wait<0>();
        __syncthreads();
        if (s + 1 < 8) {
            const float* g = U2 + (s + 1) * 4096;
            float* buf = ((s + 1) & 1) ? sm : sm + EW_OFF;
            #pragma unroll
            for (int i = 0; i < 4; ++i) { int j = tid + 256 * i; cp16(buf + j * 4, g + j * 4); }
            cp_commit();
        }
        const float* Bsb = (s & 1) ? sm : sm + EW_OFF;
        const float* hbase = Hs + (cy2 * 4) * 256;
        #pragma unroll 4
        for (int kk = 0; kk < 32; ++kk) {
            int k = s * 32 + kk;
            const ulonglong2* brow = (const ulonglong2*)(Bsb + kk * 128 + cx2 * 8);
            ulonglong2 B0 = brow[0], B1 = brow[1];
            #pragma unroll
            for (int i = 0; i < 4; ++i) {
                u64 ad = dup2(hbase[i * 256 + k]);
                acc2[i][0] = ffma2(B0.x, ad, acc2[i][0]);
                acc2[i][1] = ffma2(B0.y, ad, acc2[i][1]);
                acc2[i][2] = ffma2(B1.x, ad, acc2[i][2]);
                acc2[i][3] = ffma2(B1.y, ad, acc2[i][3]);
            }
        }
    }

    float g8[8], be8[8];
    {
        float4 t0 = *(const float4*)(gamma + cx2 * 8);
        float4 t1 = *(const float4*)(gamma + cx2 * 8 + 4);
        g8[0]=t0.x; g8[1]=t0.y; g8[2]=t0.z; g8[3]=t0.w;
        g8[4]=t1.x; g8[5]=t1.y; g8[6]=t1.z; g8[7]=t1.w;
        float4 u0 = *(const float4*)(beta + cx2 * 8);
        float4 u1 = *(const float4*)(beta + cx2 * 8 + 4);
        be8[0]=u0.x; be8[1]=u0.y; be8[2]=u0.z; be8[3]=u0.w;
        be8[4]=u1.x; be8[5]=u1.y; be8[6]=u1.z; be8[7]=u1.w;
    }
    #pragma unroll
    for (int i = 0; i < 4; ++i) {
        const int row = cy2 * 4 + i;
        const int node = nbase + row;
        float v[8];
        #pragma unroll
        for (int j = 0; j < 4; ++j) unpack2(acc2[i][j], v[2 * j], v[2 * j + 1]);
        if (node < NN) {
            const float* xr = x + (size_t)node * ND + cx2 * 8;
            float4 r0 = *(const float4*)xr, r1 = *(const float4*)(xr + 4);
            v[0]+=r0.x; v[1]+=r0.y; v[2]+=r0.z; v[3]+=r0.w;
            v[4]+=r1.x; v[5]+=r1.y; v[6]+=r1.z; v[7]+=r1.w;
        }
        float s1 = 0.f, s2 = 0.f;
        #pragma unroll
        for (int j = 0; j < 8; ++j) { s1 += v[j]; s2 += v[j] * v[j]; }
        #pragma unroll
        for (int off = 1; off < 16; off <<= 1) {
            s1 += __shfl_xor_sync(0xFFFFFFFFu, s1, off);
            s2 += __shfl_xor_sync(0xFFFFFFFFu, s2, off);
        }
        float mu = s1 * (1.f / 128.f);
        float var = s2 * (1.f / 128.f) - mu * mu;
        float r = rsqrtf(var + 1e-5f);
        if (node < NN) {
            float* op = out + (size_t)node * ND + cx2 * 8;
            float4 o0, o1;
            o0.x = (v[0]-mu)*r*g8[0]+be8[0]; o0.y = (v[1]-mu)*r*g8[1]+be8[1];
            o0.z = (v[2]-mu)*r*g8[2]+be8[2]; o0.w = (v[3]-mu)*r*g8[3]+be8[3];
            o1.x = (v[4]-mu)*r*g8[4]+be8[4]; o1.y = (v[5]-mu)*r*g8[5]+be8[5];
            o1.z = (v[6]-mu)*r*g8[6]+be8[6]; o1.w = (v[7]-mu)*r*g8[7]+be8[7];
            *(float4*)op       = o0;
            *(float4*)(op + 4) = o1;
        }
    }
}

// ---- launch --------------------------------------------------------------------
extern "C" void kernel_launch(void* const* d_in, const int* in_sizes, int n_in,
                              void* d_out, int out_size) {
    (void)in_sizes; (void)n_in; (void)out_size;
    const float* x     = (const float*)d_in[0];
    const void*  ei    = d_in[1];
    const float* ea    = (const float*)d_in[2];
    const float* W1    = (const float*)d_in[3];
    const float* b1    = (const float*)d_in[4];
    const float* W2    = (const float*)d_in[5];
    const float* b2    = (const float*)d_in[6];
    const float* U1    = (const float*)d_in[7];
    const float* c1    = (const float*)d_in[8];
    const float* U2    = (const float*)d_in[9];
    const float* c2    = (const float*)d_in[10];
    const float* gamma = (const float*)d_in[11];
    const float* beta  = (const float*)d_in[12];
    float* out = (float*)d_out;

    static bool attr_set = false;
    if (!attr_set) {
        cudaFuncSetAttribute(edge_kernel, cudaFuncAttributeMaxDynamicSharedMemorySize, EDYN);
        cudaFuncSetAttribute(node_kernel, cudaFuncAttributeMaxDynamicSharedMemorySize, NODE_SMEM);
        attr_set = true;
    }

    zero_agg_kernel<<<12500, 256>>>();
    detect_kernel<<<128, 256>>>((const unsigned*)ei);
    convert_kernel<<<(NE + 255) / 256, 256>>>(ei);
    pack_w1_kernel<<<448, 256>>>(W1);
    pack_w2_kernel<<<256, 256>>>(W2);
    edge_kernel<<<NE / 64, 256, EDYN>>>(x, ea, b1, b2);
    node_kernel<<<(NN + 63) / 64, 256, NODE_SMEM>>>(x, U1, c1, U2, c2, gamma, beta, out);
}